// round 1
// baseline (speedup 1.0000x reference)
#include <cuda_runtime.h>
#include <cstdint>

// Problem constants
#define BATCH 8
#define SEQ   1024
#define DIN   1280
#define RNK   64
#define DOUT  1280
#define EMB   (RNK*DIN + DOUT*RNK)   // 163840 per-sample embed row
#define UPOFF (RNK*DIN)              // 81920: offset of W_up within embed row

// Tiling
#define BM  64          // s-rows per CTA
#define BK  32          // k-tile for GEMM1
#define BN2 64          // n-tile for GEMM2
#define XS_STRIDE 36    // 32 + 4 pad (multiple of 4 for float4 stores, conflict-free)
#define HS_STRIDE 68    // 64 + 4 pad
#define WUS_STRIDE 68

__device__ __forceinline__ uint32_t f2tf32(float f) {
    uint32_t r;
    asm("cvt.rna.tf32.f32 %0, %1;" : "=r"(r) : "f"(f));
    return r;
}

__device__ __forceinline__ void mma8(float* c, const uint32_t* a, const uint32_t* b) {
    asm volatile(
        "mma.sync.aligned.m16n8k8.row.col.f32.tf32.tf32.f32 "
        "{%0,%1,%2,%3}, {%4,%5,%6,%7}, {%8,%9}, {%0,%1,%2,%3};"
        : "+f"(c[0]), "+f"(c[1]), "+f"(c[2]), "+f"(c[3])
        : "r"(a[0]), "r"(a[1]), "r"(a[2]), "r"(a[3]),
          "r"(b[0]), "r"(b[1]));
}

__global__ __launch_bounds__(256, 1)
void ilora_fused_kernel(const float* __restrict__ x,
                        const float* __restrict__ embed,
                        float* __restrict__ out)
{
    // Shared memory:
    //  h_s: 64 x 64 h tile (padded)
    //  buf: union of (xs 64x32 + wd 64x32) [phase 1] and wu 64x64 [phase 2]
    __shared__ float h_s[BM * HS_STRIDE];                // 4352 floats
    __shared__ float buf[2 * BM * XS_STRIDE];            // 4608 floats (>= 64*68=4352)

    float* xs = buf;
    float* wd = buf + BM * XS_STRIDE;
    float* wu = buf;

    const int t    = threadIdx.x;
    const int bb   = blockIdx.x >> 4;          // batch index (16 s-tiles per batch)
    const int m0   = (blockIdx.x & 15) * BM;   // s-row base
    const int warp = t >> 5;
    const int lane = t & 31;
    const int wm   = warp >> 2;                // 0..1 : 32 m-rows each
    const int wn   = warp & 3;                 // 0..3 : 16 n-cols each
    const int g    = lane >> 2;                // groupID 0..7
    const int tg   = lane & 3;                 // thread-in-group 0..3

    const float* xb  = x     + (size_t)bb * SEQ * DIN + (size_t)m0 * DIN;
    const float* wdb = embed + (size_t)bb * EMB;        // W_down [64, 1280]
    const float* wub = wdb + UPOFF;                     // W_up   [1280, 64]
    float*       ob  = out   + (size_t)bb * SEQ * DOUT + (size_t)m0 * DOUT;

    // ---------------- Phase 1: h[64 x 64] = X[64 x 1280] @ Wd^T ----------------
    float acc[2][2][4];
    #pragma unroll
    for (int mi = 0; mi < 2; mi++)
        #pragma unroll
        for (int ni = 0; ni < 2; ni++)
            #pragma unroll
            for (int q = 0; q < 4; q++) acc[mi][ni][q] = 0.f;

    for (int k0 = 0; k0 < DIN; k0 += BK) {
        // Load X tile (64x32) and Wd tile (64x32): 512 float4 each, 2 per thread
        #pragma unroll
        for (int i = t; i < BM * (BK / 4); i += 256) {
            int r = i >> 3;
            int c = (i & 7) * 4;
            float4 vx = *(const float4*)(xb  + (size_t)r * DIN + k0 + c);
            float4 vw = *(const float4*)(wdb + (size_t)r * DIN + k0 + c);
            *(float4*)(&xs[r * XS_STRIDE + c]) = vx;
            *(float4*)(&wd[r * XS_STRIDE + c]) = vw;
        }
        __syncthreads();

        #pragma unroll
        for (int ks = 0; ks < BK / 8; ks++) {
            const int kb = ks * 8;
            uint32_t afr[2][4];
            #pragma unroll
            for (int mi = 0; mi < 2; mi++) {
                int r = wm * 32 + mi * 16 + g;
                afr[mi][0] = f2tf32(xs[r       * XS_STRIDE + kb + tg]);
                afr[mi][1] = f2tf32(xs[(r + 8) * XS_STRIDE + kb + tg]);
                afr[mi][2] = f2tf32(xs[r       * XS_STRIDE + kb + tg + 4]);
                afr[mi][3] = f2tf32(xs[(r + 8) * XS_STRIDE + kb + tg + 4]);
            }
            uint32_t bfr[2][2];
            #pragma unroll
            for (int ni = 0; ni < 2; ni++) {
                int n = wn * 16 + ni * 8 + g;
                bfr[ni][0] = f2tf32(wd[n * XS_STRIDE + kb + tg]);
                bfr[ni][1] = f2tf32(wd[n * XS_STRIDE + kb + tg + 4]);
            }
            #pragma unroll
            for (int mi = 0; mi < 2; mi++)
                #pragma unroll
                for (int ni = 0; ni < 2; ni++)
                    mma8(acc[mi][ni], afr[mi], bfr[ni]);
        }
        __syncthreads();
    }

    // Park h in shared memory (C-fragment layout -> row-major tile)
    #pragma unroll
    for (int mi = 0; mi < 2; mi++) {
        #pragma unroll
        for (int ni = 0; ni < 2; ni++) {
            int r = wm * 32 + mi * 16 + g;
            int c = wn * 16 + ni * 8 + tg * 2;
            *(float2*)(&h_s[r       * HS_STRIDE + c]) = make_float2(acc[mi][ni][0], acc[mi][ni][1]);
            *(float2*)(&h_s[(r + 8) * HS_STRIDE + c]) = make_float2(acc[mi][ni][2], acc[mi][ni][3]);
        }
    }
    __syncthreads();

    // Preload ALL A-fragments of h into registers (reused across all 20 n-tiles):
    // 2 m-tiles x 8 k-steps x 4 regs = 64 regs/thread.
    uint32_t ah[2][8][4];
    #pragma unroll
    for (int mi = 0; mi < 2; mi++) {
        int r = wm * 32 + mi * 16 + g;
        #pragma unroll
        for (int ks = 0; ks < 8; ks++) {
            int kb = ks * 8;
            ah[mi][ks][0] = f2tf32(h_s[r       * HS_STRIDE + kb + tg]);
            ah[mi][ks][1] = f2tf32(h_s[(r + 8) * HS_STRIDE + kb + tg]);
            ah[mi][ks][2] = f2tf32(h_s[r       * HS_STRIDE + kb + tg + 4]);
            ah[mi][ks][3] = f2tf32(h_s[(r + 8) * HS_STRIDE + kb + tg + 4]);
        }
    }

    // ---------------- Phase 2: out[64 x 1280] = h[64 x 64] @ Wu^T ----------------
    for (int n0 = 0; n0 < DOUT; n0 += BN2) {
        __syncthreads();   // previous iter's wu reads done before overwrite
        // Load Wu tile: rows n0..n0+63 of W_up [1280, 64] -> wu[n][r], 4 float4 per thread
        #pragma unroll
        for (int i = t; i < BM * (RNK / 4); i += 256) {
            int rr = i >> 4;
            int c  = (i & 15) * 4;
            float4 v = *(const float4*)(wub + (size_t)(n0 + rr) * RNK + c);
            *(float4*)(&wu[rr * WUS_STRIDE + c]) = v;
        }
        __syncthreads();

        float o[2][2][4];
        #pragma unroll
        for (int mi = 0; mi < 2; mi++)
            #pragma unroll
            for (int ni = 0; ni < 2; ni++)
                #pragma unroll
                for (int q = 0; q < 4; q++) o[mi][ni][q] = 0.f;

        #pragma unroll
        for (int ks = 0; ks < 8; ks++) {
            uint32_t bfr[2][2];
            #pragma unroll
            for (int ni = 0; ni < 2; ni++) {
                int n = wn * 16 + ni * 8 + g;
                bfr[ni][0] = f2tf32(wu[n * WUS_STRIDE + ks * 8 + tg]);
                bfr[ni][1] = f2tf32(wu[n * WUS_STRIDE + ks * 8 + tg + 4]);
            }
            #pragma unroll
            for (int mi = 0; mi < 2; mi++)
                #pragma unroll
                for (int ni = 0; ni < 2; ni++)
                    mma8(o[mi][ni], ah[mi][ks], bfr[ni]);
        }

        // Epilogue: float2 stores (8B aligned; col even)
        #pragma unroll
        for (int mi = 0; mi < 2; mi++) {
            #pragma unroll
            for (int ni = 0; ni < 2; ni++) {
                int r = wm * 32 + mi * 16 + g;
                int c = n0 + wn * 16 + ni * 8 + tg * 2;
                *(float2*)(ob + (size_t)r       * DOUT + c) = make_float2(o[mi][ni][0], o[mi][ni][1]);
                *(float2*)(ob + (size_t)(r + 8) * DOUT + c) = make_float2(o[mi][ni][2], o[mi][ni][3]);
            }
        }
    }
}

extern "C" void kernel_launch(void* const* d_in, const int* in_sizes, int n_in,
                              void* d_out, int out_size)
{
    (void)in_sizes; (void)n_in; (void)out_size;
    const float* x     = (const float*)d_in[0];
    const float* embed = (const float*)d_in[1];
    float*       out   = (float*)d_out;

    // 8 batches x 16 s-tiles of 64 rows = 128 CTAs, 256 threads each
    ilora_fused_kernel<<<BATCH * (SEQ / BM), 256>>>(x, embed, out);
}

// round 2
// speedup vs baseline: 1.1373x; 1.1373x over previous
#include <cuda_runtime.h>
#include <cstdint>

// Problem constants
#define BATCH 8
#define SEQ   1024
#define DIN   1280
#define RNK   64
#define DOUT  1280
#define EMB   (RNK*DIN + DOUT*RNK)   // 163840 per-sample embed row
#define UPOFF (RNK*DIN)              // 81920: offset of W_up within embed row

// Tiling
#define BM  64          // s-rows per CTA
#define BK  32          // k-tile for GEMM1
#define BN2 64          // n-tile for GEMM2
#define XS_STRIDE 36    // 32 + 4 pad -> conflict-free (g*4+tg pattern)
#define HS_STRIDE 68    // 64 + 4 pad
#define WUS_STRIDE 68

// Shared memory layout (floats), 4-stage GEMM1 pipeline:
//   stage s: xs at s*4608, wd at s*4608+2304   (4 stages = 18432 floats = 73728 B)
// After GEMM1 (regions dead, sync-ordered):
//   h   at [0, 4352)
//   wu0 at [4352, 8704), wu1 at [8704, 13056), wu2 at [13056, 17408)
#define STAGE_F 4608
#define SMEM_BYTES (4 * STAGE_F * 4)
#define H_OFF   0
#define WU0_OFF 4352
#define WU1_OFF 8704
#define WU2_OFF 13056

__device__ __forceinline__ uint32_t f2tf32(float f) {
    uint32_t r;
    asm("cvt.rna.tf32.f32 %0, %1;" : "=r"(r) : "f"(f));
    return r;
}

__device__ __forceinline__ void mma8(float* c, const uint32_t* a, const uint32_t* b) {
    asm volatile(
        "mma.sync.aligned.m16n8k8.row.col.f32.tf32.tf32.f32 "
        "{%0,%1,%2,%3}, {%4,%5,%6,%7}, {%8,%9}, {%0,%1,%2,%3};"
        : "+f"(c[0]), "+f"(c[1]), "+f"(c[2]), "+f"(c[3])
        : "r"(a[0]), "r"(a[1]), "r"(a[2]), "r"(a[3]),
          "r"(b[0]), "r"(b[1]));
}

__device__ __forceinline__ void cp16(uint32_t sdst, const void* g) {
    asm volatile("cp.async.cg.shared.global [%0], [%1], 16;"
                 :: "r"(sdst), "l"(g) : "memory");
}
__device__ __forceinline__ void cp_commit() {
    asm volatile("cp.async.commit_group;" ::: "memory");
}
template <int N>
__device__ __forceinline__ void cp_wait() {
    asm volatile("cp.async.wait_group %0;" :: "n"(N) : "memory");
}

extern __shared__ float sm[];

__global__ __launch_bounds__(512, 1)
void ilora_fused_kernel(const float* __restrict__ x,
                        const float* __restrict__ embed,
                        float* __restrict__ out)
{
    const int t    = threadIdx.x;
    const int bb   = blockIdx.x >> 4;          // batch index
    const int m0   = (blockIdx.x & 15) * BM;   // s-row base
    const int warp = t >> 5;
    const int lane = t & 31;
    const int wm   = warp >> 3;                // 0..1 : 32 m-rows each
    const int wn   = warp & 7;                 // 0..7 : 8 n-cols each
    const int g    = lane >> 2;                // groupID 0..7
    const int tg   = lane & 3;                 // thread-in-group 0..3

    const float* xb  = x     + (size_t)bb * SEQ * DIN + (size_t)m0 * DIN;
    const float* wdb = embed + (size_t)bb * EMB;        // W_down [64, 1280]
    const float* wub = wdb + UPOFF;                     // W_up   [1280, 64]
    float*       ob  = out   + (size_t)bb * SEQ * DOUT + (size_t)m0 * DOUT;

    const uint32_t smem_u32 = (uint32_t)__cvta_generic_to_shared(sm);

    // ---------------- Phase 1: h[64 x 64] = X[64 x 1280] @ Wd^T ----------------
    // Loader mapping: one float4 of X and one of Wd per thread per k-tile.
    const int lr = t >> 3;          // 0..63
    const int lc = (t & 7) * 4;     // 0,4,...,28
    const float* gx = xb  + (size_t)lr * DIN + lc;
    const float* gw = wdb + (size_t)lr * DIN + lc;
    const uint32_t s_ld = smem_u32 + (uint32_t)(lr * XS_STRIDE + lc) * 4;

    #define LOAD_KTILE(kt) do {                                     \
        uint32_t so = (uint32_t)(((kt) & 3) * STAGE_F) * 4;         \
        cp16(s_ld + so,            gx + (kt) * BK);                 \
        cp16(s_ld + so + 2304 * 4, gw + (kt) * BK);                 \
        cp_commit();                                                \
    } while (0)

    LOAD_KTILE(0);
    LOAD_KTILE(1);
    LOAD_KTILE(2);

    float acc[2][4];
    #pragma unroll
    for (int mi = 0; mi < 2; mi++)
        #pragma unroll
        for (int q = 0; q < 4; q++) acc[mi][q] = 0.f;

    #pragma unroll 1
    for (int kt = 0; kt < 40; kt++) {
        int rem = 39 - kt;
        if (rem >= 2)      cp_wait<2>();
        else if (rem == 1) cp_wait<1>();
        else               cp_wait<0>();
        __syncthreads();

        const float* xs  = sm + (kt & 3) * STAGE_F;
        const float* wdp = xs + 2304;

        #pragma unroll
        for (int ks = 0; ks < 4; ks++) {
            const int kb = ks * 8;
            uint32_t afr[2][4];
            #pragma unroll
            for (int mi = 0; mi < 2; mi++) {
                int r = wm * 32 + mi * 16 + g;
                afr[mi][0] = f2tf32(xs[r       * XS_STRIDE + kb + tg]);
                afr[mi][1] = f2tf32(xs[(r + 8) * XS_STRIDE + kb + tg]);
                afr[mi][2] = f2tf32(xs[r       * XS_STRIDE + kb + tg + 4]);
                afr[mi][3] = f2tf32(xs[(r + 8) * XS_STRIDE + kb + tg + 4]);
            }
            uint32_t bfr[2];
            {
                int n = wn * 8 + g;
                bfr[0] = f2tf32(wdp[n * XS_STRIDE + kb + tg]);
                bfr[1] = f2tf32(wdp[n * XS_STRIDE + kb + tg + 4]);
            }
            #pragma unroll
            for (int mi = 0; mi < 2; mi++)
                mma8(acc[mi], afr[mi], bfr);
        }

        if (kt + 3 < 40) LOAD_KTILE(kt + 3);
    }

    // Park h in shared memory (stage regions are dead; sync-ordered by the
    // begin-of-iter barriers above). Each warp writes only its own fragment.
    {
        float* h_s = sm + H_OFF;
        #pragma unroll
        for (int mi = 0; mi < 2; mi++) {
            int r = wm * 32 + mi * 16 + g;
            int c = wn * 8 + tg * 2;
            *(float2*)(&h_s[r       * HS_STRIDE + c]) = make_float2(acc[mi][0], acc[mi][1]);
            *(float2*)(&h_s[(r + 8) * HS_STRIDE + c]) = make_float2(acc[mi][2], acc[mi][3]);
        }
    }

    // Prefetch W_up tiles 0 and 1 (target regions don't overlap h).
    const int WU_OFFS[3] = {WU0_OFF, WU1_OFF, WU2_OFF};
    #define LOAD_WUTILE(j) do {                                               \
        int _buf = WU_OFFS[(j) % 3];                                          \
        _Pragma("unroll")                                                     \
        for (int i = t; i < 1024; i += 512) {                                 \
            int rr = i >> 4;                                                  \
            int cc = (i & 15) * 4;                                            \
            cp16(smem_u32 + (uint32_t)(_buf + rr * WUS_STRIDE + cc) * 4,      \
                 wub + (size_t)((j) * BN2 + rr) * RNK + cc);                  \
        }                                                                     \
        cp_commit();                                                          \
    } while (0)

    LOAD_WUTILE(0);
    LOAD_WUTILE(1);

    __syncthreads();   // h visible to all warps

    // Preload ALL A-fragments of h into registers (reused across 20 n-tiles).
    uint32_t ah[2][8][4];
    {
        const float* h_s = sm + H_OFF;
        #pragma unroll
        for (int mi = 0; mi < 2; mi++) {
            int r = wm * 32 + mi * 16 + g;
            #pragma unroll
            for (int ks = 0; ks < 8; ks++) {
                int kb = ks * 8;
                ah[mi][ks][0] = f2tf32(h_s[r       * HS_STRIDE + kb + tg]);
                ah[mi][ks][1] = f2tf32(h_s[(r + 8) * HS_STRIDE + kb + tg]);
                ah[mi][ks][2] = f2tf32(h_s[r       * HS_STRIDE + kb + tg + 4]);
                ah[mi][ks][3] = f2tf32(h_s[(r + 8) * HS_STRIDE + kb + tg + 4]);
            }
        }
    }

    // ---------------- Phase 2: out[64 x 1280] = h @ Wu^T, triple-buffered ----------------
    #pragma unroll 1
    for (int j = 0; j < 20; j++) {
        if (j < 19) cp_wait<1>();
        else        cp_wait<0>();
        __syncthreads();

        const float* wup = sm + WU_OFFS[j % 3];

        float o[2][4];
        #pragma unroll
        for (int mi = 0; mi < 2; mi++)
            #pragma unroll
            for (int q = 0; q < 4; q++) o[mi][q] = 0.f;

        #pragma unroll
        for (int ks = 0; ks < 8; ks++) {
            uint32_t bfr[2];
            int n = wn * 8 + g;
            bfr[0] = f2tf32(wup[n * WUS_STRIDE + ks * 8 + tg]);
            bfr[1] = f2tf32(wup[n * WUS_STRIDE + ks * 8 + tg + 4]);
            #pragma unroll
            for (int mi = 0; mi < 2; mi++)
                mma8(o[mi], ah[mi][ks], bfr);
        }

        // Epilogue: float2 coalesced stores
        const int n0 = j * BN2;
        #pragma unroll
        for (int mi = 0; mi < 2; mi++) {
            int r = wm * 32 + mi * 16 + g;
            int c = n0 + wn * 8 + tg * 2;
            *(float2*)(ob + (size_t)r       * DOUT + c) = make_float2(o[mi][0], o[mi][1]);
            *(float2*)(ob + (size_t)(r + 8) * DOUT + c) = make_float2(o[mi][2], o[mi][3]);
        }

        if (j + 2 < 20) LOAD_WUTILE(j + 2);
    }
}

extern "C" void kernel_launch(void* const* d_in, const int* in_sizes, int n_in,
                              void* d_out, int out_size)
{
    (void)in_sizes; (void)n_in; (void)out_size;
    const float* x     = (const float*)d_in[0];
    const float* embed = (const float*)d_in[1];
    float*       out   = (float*)d_out;

    cudaFuncSetAttribute(ilora_fused_kernel,
                         cudaFuncAttributeMaxDynamicSharedMemorySize, SMEM_BYTES);

    ilora_fused_kernel<<<BATCH * (SEQ / BM), 512, SMEM_BYTES>>>(x, embed, out);
}